// round 4
// baseline (speedup 1.0000x reference)
#include <cuda_runtime.h>
#include <cuda_bf16.h>
#include <math.h>
#include <cstdint>

#define NB 4096
#define ND 128
#define TILE 128
#define STRIDE 272              // smem bytes per 128-col bf16 row (256 + 16 pad)
#define SM_TILE (128 * STRIDE)  // 34816 B per tile
#define SM_TOTAL (2 * SM_TILE)  // 69632 B

// ---------------- scratch (no allocations allowed) ----------------
__device__ __align__(16) uint2 g_zi_bf[NB * 32];   // bf16 z_i, 4 bf16 per uint2
__device__ __align__(16) uint2 g_zj_bf[NB * 32];   // bf16 z_j
__device__ float g_rowsum[NB];
__device__ float g_colsum[NB];
__device__ float g_pos[NB];

__device__ __forceinline__ uint32_t smem_u32(const void* p) {
    uint32_t a;
    asm("{ .reg .u64 t; cvta.to.shared.u64 t, %1; cvt.u32.u64 %0, t; }" : "=r"(a) : "l"(p));
    return a;
}
__device__ __forceinline__ void ldm_x4(uint32_t& r0, uint32_t& r1, uint32_t& r2,
                                       uint32_t& r3, uint32_t addr) {
    asm volatile("ldmatrix.sync.aligned.m8n8.x4.shared.b16 {%0,%1,%2,%3}, [%4];"
                 : "=r"(r0), "=r"(r1), "=r"(r2), "=r"(r3) : "r"(addr));
}
__device__ __forceinline__ void mma_16816(float& c0, float& c1, float& c2, float& c3,
                                          uint32_t a0, uint32_t a1, uint32_t a2, uint32_t a3,
                                          uint32_t b0, uint32_t b1) {
    asm volatile("mma.sync.aligned.m16n8k16.row.col.f32.bf16.bf16.f32 "
                 "{%0,%1,%2,%3}, {%4,%5,%6,%7}, {%8,%9}, {%0,%1,%2,%3};"
                 : "+f"(c0), "+f"(c1), "+f"(c2), "+f"(c3)
                 : "r"(a0), "r"(a1), "r"(a2), "r"(a3), "r"(b0), "r"(b1));
}

// ---------------------------------------------------------------------------
// Kernel 1: 2 rows per warp, front-batched loads (MLP=4/thread).
// ---------------------------------------------------------------------------
__global__ void __launch_bounds__(256) norm_kernel(const float* __restrict__ emb_i,
                                                   const float* __restrict__ emb_j) {
    int lane = threadIdx.x & 31;
    int w = threadIdx.x >> 5;
    int r0 = blockIdx.x * 16 + w * 2;          // this warp: rows r0, r0+1
    const float4* EI = (const float4*)emb_i;
    const float4* EJ = (const float4*)emb_j;
    float4 a0 = EI[r0 * 32 + lane];
    float4 b0 = EJ[r0 * 32 + lane];
    float4 a1 = EI[(r0 + 1) * 32 + lane];
    float4 b1 = EJ[(r0 + 1) * 32 + lane];

    float s0i = a0.x*a0.x + a0.y*a0.y + a0.z*a0.z + a0.w*a0.w;
    float s0j = b0.x*b0.x + b0.y*b0.y + b0.z*b0.z + b0.w*b0.w;
    float d0  = a0.x*b0.x + a0.y*b0.y + a0.z*b0.z + a0.w*b0.w;
    float s1i = a1.x*a1.x + a1.y*a1.y + a1.z*a1.z + a1.w*a1.w;
    float s1j = b1.x*b1.x + b1.y*b1.y + b1.z*b1.z + b1.w*b1.w;
    float d1  = a1.x*b1.x + a1.y*b1.y + a1.z*b1.z + a1.w*b1.w;
#pragma unroll
    for (int o = 16; o > 0; o >>= 1) {
        s0i += __shfl_xor_sync(0xffffffffu, s0i, o);
        s0j += __shfl_xor_sync(0xffffffffu, s0j, o);
        d0  += __shfl_xor_sync(0xffffffffu, d0,  o);
        s1i += __shfl_xor_sync(0xffffffffu, s1i, o);
        s1j += __shfl_xor_sync(0xffffffffu, s1j, o);
        d1  += __shfl_xor_sync(0xffffffffu, d1,  o);
    }
    float i0 = 1.0f / fmaxf(sqrtf(s0i), 1e-12f);
    float j0 = 1.0f / fmaxf(sqrtf(s0j), 1e-12f);
    float i1 = 1.0f / fmaxf(sqrtf(s1i), 1e-12f);
    float j1 = 1.0f / fmaxf(sqrtf(s1j), 1e-12f);

    uint2 o0, o1;
    float zx, zy, zz, zw;
    zx = a0.x*i0; zy = a0.y*i0; zz = a0.z*i0; zw = a0.w*i0;
    asm("cvt.rn.bf16x2.f32 %0, %1, %2;" : "=r"(o0.x) : "f"(zy), "f"(zx));
    asm("cvt.rn.bf16x2.f32 %0, %1, %2;" : "=r"(o0.y) : "f"(zw), "f"(zz));
    zx = b0.x*j0; zy = b0.y*j0; zz = b0.z*j0; zw = b0.w*j0;
    asm("cvt.rn.bf16x2.f32 %0, %1, %2;" : "=r"(o1.x) : "f"(zy), "f"(zx));
    asm("cvt.rn.bf16x2.f32 %0, %1, %2;" : "=r"(o1.y) : "f"(zw), "f"(zz));
    g_zi_bf[r0 * 32 + lane] = o0;
    g_zj_bf[r0 * 32 + lane] = o1;
    zx = a1.x*i1; zy = a1.y*i1; zz = a1.z*i1; zw = a1.w*i1;
    asm("cvt.rn.bf16x2.f32 %0, %1, %2;" : "=r"(o0.x) : "f"(zy), "f"(zx));
    asm("cvt.rn.bf16x2.f32 %0, %1, %2;" : "=r"(o0.y) : "f"(zw), "f"(zz));
    zx = b1.x*j1; zy = b1.y*j1; zz = b1.z*j1; zw = b1.w*j1;
    asm("cvt.rn.bf16x2.f32 %0, %1, %2;" : "=r"(o1.x) : "f"(zy), "f"(zx));
    asm("cvt.rn.bf16x2.f32 %0, %1, %2;" : "=r"(o1.y) : "f"(zw), "f"(zz));
    g_zi_bf[(r0 + 1) * 32 + lane] = o0;
    g_zj_bf[(r0 + 1) * 32 + lane] = o1;

    if (lane == 0) {
        g_pos[r0]        = d0 * i0 * j0;
        g_rowsum[r0]     = 0.0f;
        g_colsum[r0]     = 0.0f;
        g_pos[r0 + 1]    = d1 * i1 * j1;
        g_rowsum[r0 + 1] = 0.0f;
        g_colsum[r0 + 1] = 0.0f;
    }
}

// ---------------------------------------------------------------------------
// Kernel 2: 128x128 S-tile via mma.sync bf16, fused exp + row/col sums.
// 16 warps: 4(m) x 4(n); each warp 32x32 = 2 m-frags x 4 n-frags of 16x8.
// ---------------------------------------------------------------------------
__global__ void __launch_bounds__(512, 2) sim_kernel() {
    extern __shared__ char smem[];
    __shared__ float srow[TILE];
    __shared__ float scol[TILE];

    uint32_t sA = smem_u32(smem);
    uint32_t sB = sA + SM_TILE;
    int tid = threadIdx.x;
    int wid = tid >> 5;
    int l = tid & 31;
    int rowBase = blockIdx.y * TILE;
    int colBase = blockIdx.x * TILE;
    int m_base = (wid & 3) * 32;
    int n_base = (wid >> 2) * 32;

    if (tid < TILE) { srow[tid] = 0.0f; scol[tid] = 0.0f; }

    // --- global -> smem (16B chunks); row stride 272 B: ldmatrix conflict-free
    const uint4* gi = (const uint4*)(g_zi_bf + rowBase * 32);   // 16 uint4/row
    const uint4* gj = (const uint4*)(g_zj_bf + colBase * 32);
#pragma unroll
    for (int it = 0; it < 4; it++) {
        int i = it * 512 + tid;              // [0, 2048)
        int row = i >> 4, chunk = i & 15;
        uint32_t off = (uint32_t)row * STRIDE + chunk * 16;
        *(uint4*)(smem + off) = gi[i];
        *(uint4*)(smem + SM_TILE + off) = gj[i];
    }
    __syncthreads();

    // per-lane ldmatrix base (x4: lanes 0-7/8-15/16-23/24-31 -> 4 matrices)
    uint32_t lrow  = (uint32_t)(((l >> 3) & 1) * 8 + (l & 7));
    uint32_t lcolb = (uint32_t)((l >> 4) * 16);
    uint32_t a_base = sA + (m_base + lrow) * STRIDE + lcolb;
    uint32_t b_base = sB + (n_base + lrow) * STRIDE + lcolb;

    float c[2][4][4];
#pragma unroll
    for (int mf = 0; mf < 2; mf++)
#pragma unroll
        for (int nf = 0; nf < 4; nf++)
#pragma unroll
            for (int e = 0; e < 4; e++) c[mf][nf][e] = 0.0f;

#pragma unroll
    for (int ks = 0; ks < 8; ks++) {
        uint32_t koff = (uint32_t)ks * 32;                      // 16 bf16 = 32 B
        uint32_t a0[2], a1[2], a2[2], a3[2];
#pragma unroll
        for (int mf = 0; mf < 2; mf++)
            ldm_x4(a0[mf], a1[mf], a2[mf], a3[mf],
                   a_base + (uint32_t)mf * 16 * STRIDE + koff);
        uint32_t bl0[2], bl1[2], bl2[2], bl3[2];
#pragma unroll
        for (int nh = 0; nh < 2; nh++)
            ldm_x4(bl0[nh], bl1[nh], bl2[nh], bl3[nh],
                   b_base + (uint32_t)nh * 16 * STRIDE + koff);
#pragma unroll
        for (int mf = 0; mf < 2; mf++) {
#pragma unroll
            for (int nh = 0; nh < 2; nh++) {
                mma_16816(c[mf][nh * 2][0], c[mf][nh * 2][1],
                          c[mf][nh * 2][2], c[mf][nh * 2][3],
                          a0[mf], a1[mf], a2[mf], a3[mf], bl0[nh], bl2[nh]);
                mma_16816(c[mf][nh * 2 + 1][0], c[mf][nh * 2 + 1][1],
                          c[mf][nh * 2 + 1][2], c[mf][nh * 2 + 1][3],
                          a0[mf], a1[mf], a2[mf], a3[mf], bl1[nh], bl3[nh]);
            }
        }
    }

    // --- epilogue: exp + in-register row/col partial sums ---
    // elem map: c0:(r,cc) c1:(r,cc+1) c2:(r+8,cc) c3:(r+8,cc+1); r=l/4, cc=2(l%4)
    float rlo[2], rhi[2], ceven[4], codd[4];
#pragma unroll
    for (int i = 0; i < 4; i++) { ceven[i] = 0.0f; codd[i] = 0.0f; }
#pragma unroll
    for (int mf = 0; mf < 2; mf++) { rlo[mf] = 0.0f; rhi[mf] = 0.0f; }
#pragma unroll
    for (int mf = 0; mf < 2; mf++) {
#pragma unroll
        for (int nf = 0; nf < 4; nf++) {
            float e0 = __expf(c[mf][nf][0] * 4.0f);   // 1/T = 4
            float e1 = __expf(c[mf][nf][1] * 4.0f);
            float e2 = __expf(c[mf][nf][2] * 4.0f);
            float e3 = __expf(c[mf][nf][3] * 4.0f);
            rlo[mf] += e0 + e1;
            rhi[mf] += e2 + e3;
            ceven[nf] += e0 + e2;
            codd[nf]  += e1 + e3;
        }
    }
#pragma unroll
    for (int mf = 0; mf < 2; mf++) {
#pragma unroll
        for (int o = 1; o <= 2; o <<= 1) {
            rlo[mf] += __shfl_xor_sync(0xffffffffu, rlo[mf], o);
            rhi[mf] += __shfl_xor_sync(0xffffffffu, rhi[mf], o);
        }
        if ((l & 3) == 0) {
            int r = m_base + mf * 16 + (l >> 2);
            atomicAdd(&srow[r], rlo[mf]);
            atomicAdd(&srow[r + 8], rhi[mf]);
        }
    }
#pragma unroll
    for (int nf = 0; nf < 4; nf++) {
#pragma unroll
        for (int o = 4; o <= 16; o <<= 1) {
            ceven[nf] += __shfl_xor_sync(0xffffffffu, ceven[nf], o);
            codd[nf]  += __shfl_xor_sync(0xffffffffu, codd[nf], o);
        }
        if (l < 4) {
            int cc = n_base + nf * 8 + 2 * l;
            atomicAdd(&scol[cc], ceven[nf]);
            atomicAdd(&scol[cc + 1], codd[nf]);
        }
    }
    __syncthreads();

    if (tid < TILE) {
        atomicAdd(&g_rowsum[rowBase + tid], srow[tid]);
        atomicAdd(&g_colsum[colBase + tid], scol[tid]);
    }
}

// ---------------------------------------------------------------------------
// Kernel 3: loss = ( sum log(rowsum)+log(colsum) - (2/T) sum pos ) / 2B
// ---------------------------------------------------------------------------
__global__ void __launch_bounds__(512) final_kernel(float* __restrict__ out) {
    int t = threadIdx.x;
    double acc = 0.0;
    for (int i = t; i < NB; i += 512) {
        acc += (double)__logf(g_rowsum[i]) + (double)__logf(g_colsum[i])
             - 8.0 * (double)g_pos[i];                        // 2/T = 8
    }
    __shared__ double sd[512];
    sd[t] = acc;
    __syncthreads();
#pragma unroll
    for (int o = 256; o > 0; o >>= 1) {
        if (t < o) sd[t] += sd[t + o];
        __syncthreads();
    }
    if (t == 0) out[0] = (float)(sd[0] / (2.0 * NB));
}

extern "C" void kernel_launch(void* const* d_in, const int* in_sizes, int n_in,
                              void* d_out, int out_size) {
    const float* emb_i = (const float*)d_in[0];
    const float* emb_j = (const float*)d_in[1];
    float* out = (float*)d_out;

    cudaFuncSetAttribute(sim_kernel, cudaFuncAttributeMaxDynamicSharedMemorySize, SM_TOTAL);

    norm_kernel<<<NB / 16, 256>>>(emb_i, emb_j);
    dim3 grid(NB / TILE, NB / TILE);       // 32 x 32
    sim_kernel<<<grid, 512, SM_TOTAL>>>();
    final_kernel<<<1, 512>>>(out);
}

// round 5
// speedup vs baseline: 1.2537x; 1.2537x over previous
#include <cuda_runtime.h>
#include <cuda_bf16.h>
#include <math.h>
#include <cstdint>

#define NB 4096
#define ND 128
#define TILE 128
#define STRIDE 144              // smem bytes per 128-col fp8 row (128 + 16 pad)
#define SM_TILE (128 * STRIDE)  // 18432 B per tile
#define SM_TOTAL (2 * SM_TILE)  // 36864 B
#define EXP_SCALE 0.015625f     // (1/T) / 256 = 4/256 (z scaled by 16 each side)

// ---------------- scratch (no allocations allowed) ----------------
__device__ __align__(16) uint32_t g_zi_f8[NB * 32];  // e4m3 z_i*16, 4 per uint
__device__ __align__(16) uint32_t g_zj_f8[NB * 32];  // e4m3 z_j*16
__device__ float g_rowsum[NB];
__device__ float g_colsum[NB];
__device__ float g_pos[NB];

__device__ __forceinline__ uint32_t smem_u32(const void* p) {
    uint32_t a;
    asm("{ .reg .u64 t; cvta.to.shared.u64 t, %1; cvt.u32.u64 %0, t; }" : "=r"(a) : "l"(p));
    return a;
}
__device__ __forceinline__ void ldm_x4(uint32_t& r0, uint32_t& r1, uint32_t& r2,
                                       uint32_t& r3, uint32_t addr) {
    asm volatile("ldmatrix.sync.aligned.m8n8.x4.shared.b16 {%0,%1,%2,%3}, [%4];"
                 : "=r"(r0), "=r"(r1), "=r"(r2), "=r"(r3) : "r"(addr));
}
__device__ __forceinline__ void mma_fp8(float& c0, float& c1, float& c2, float& c3,
                                        uint32_t a0, uint32_t a1, uint32_t a2, uint32_t a3,
                                        uint32_t b0, uint32_t b1) {
    asm volatile("mma.sync.aligned.m16n8k32.row.col.f32.e4m3.e4m3.f32 "
                 "{%0,%1,%2,%3}, {%4,%5,%6,%7}, {%8,%9}, {%0,%1,%2,%3};"
                 : "+f"(c0), "+f"(c1), "+f"(c2), "+f"(c3)
                 : "r"(a0), "r"(a1), "r"(a2), "r"(a3), "r"(b0), "r"(b1));
}
__device__ __forceinline__ uint32_t pack_e4m3(float x, float y, float z, float w) {
    uint16_t lo, hi;
    asm("cvt.rn.satfinite.e4m3x2.f32 %0, %1, %2;" : "=h"(lo) : "f"(y), "f"(x));
    asm("cvt.rn.satfinite.e4m3x2.f32 %0, %1, %2;" : "=h"(hi) : "f"(w), "f"(z));
    return (uint32_t)lo | ((uint32_t)hi << 16);
}

// ---------------------------------------------------------------------------
// Kernel 1: warp-per-row L2 normalize, write e4m3 z*16, fp32 positives, zero sums
// ---------------------------------------------------------------------------
__global__ void __launch_bounds__(256) norm_kernel(const float* __restrict__ emb_i,
                                                   const float* __restrict__ emb_j) {
    int lane = threadIdx.x & 31;
    int row = blockIdx.x * 8 + (threadIdx.x >> 5);
    const float4 a = ((const float4*)emb_i)[row * 32 + lane];
    const float4 b = ((const float4*)emb_j)[row * 32 + lane];
    float ssi = a.x * a.x + a.y * a.y + a.z * a.z + a.w * a.w;
    float ssj = b.x * b.x + b.y * b.y + b.z * b.z + b.w * b.w;
    float dot = a.x * b.x + a.y * b.y + a.z * b.z + a.w * b.w;
#pragma unroll
    for (int o = 16; o > 0; o >>= 1) {
        ssi += __shfl_xor_sync(0xffffffffu, ssi, o);
        ssj += __shfl_xor_sync(0xffffffffu, ssj, o);
        dot += __shfl_xor_sync(0xffffffffu, dot, o);
    }
    float inv_i = 1.0f / fmaxf(sqrtf(ssi), 1e-12f);
    float inv_j = 1.0f / fmaxf(sqrtf(ssj), 1e-12f);
    float si = inv_i * 16.0f;   // scale into e4m3 normal range
    float sj = inv_j * 16.0f;

    g_zi_f8[row * 32 + lane] = pack_e4m3(a.x * si, a.y * si, a.z * si, a.w * si);
    g_zj_f8[row * 32 + lane] = pack_e4m3(b.x * sj, b.y * sj, b.z * sj, b.w * sj);
    if (lane == 0) {
        g_pos[row]    = dot * inv_i * inv_j;   // exact fp32 positive
        g_rowsum[row] = 0.0f;
        g_colsum[row] = 0.0f;
    }
}

// ---------------------------------------------------------------------------
// Kernel 2: 128x128 S-tile via mma.sync fp8 (m16n8k32), fused exp + row/col sums.
// 8 warps: 2(m) x 4(n); each warp 64x32 = 4 m-frags x 4 n-frags of 16x8.
// ---------------------------------------------------------------------------
__global__ void __launch_bounds__(256) sim_kernel() {
    extern __shared__ char smem[];
    __shared__ float srow[TILE];
    __shared__ float scol[TILE];

    uint32_t sA = smem_u32(smem);
    uint32_t sB = sA + SM_TILE;
    int tid = threadIdx.x;
    int wid = tid >> 5;
    int l = tid & 31;
    int rowBase = blockIdx.y * TILE;
    int colBase = blockIdx.x * TILE;
    int m_base = (wid & 1) * 64;
    int n_base = (wid >> 1) * 32;

    if (tid < TILE) { srow[tid] = 0.0f; scol[tid] = 0.0f; }

    // --- global -> smem (16B chunks); 128B fp8 row + 16B pad: conflict-free
    const uint4* gi = (const uint4*)(g_zi_f8 + rowBase * 32);   // 8 uint4/row
    const uint4* gj = (const uint4*)(g_zj_f8 + colBase * 32);
#pragma unroll
    for (int it = 0; it < 4; it++) {
        int i = it * 256 + tid;              // [0, 1024)
        int row = i >> 3, chunk = i & 7;
        uint32_t off = (uint32_t)row * STRIDE + chunk * 16;
        *(uint4*)(smem + off) = gi[i];
        *(uint4*)(smem + SM_TILE + off) = gj[i];
    }
    __syncthreads();

    // per-lane ldmatrix base: x4 -> (rows0-7,k0-15),(rows8-15,k0-15),
    // (rows0-7,k16-31),(rows8-15,k16-31); byte-compatible with fp8 fragments.
    uint32_t lrow  = (uint32_t)(((l >> 3) & 1) * 8 + (l & 7));
    uint32_t lcolb = (uint32_t)((l >> 4) * 16);
    uint32_t a_base = sA + (m_base + lrow) * STRIDE + lcolb;
    uint32_t b_base = sB + (n_base + lrow) * STRIDE + lcolb;

    float c[4][4][4];
#pragma unroll
    for (int mf = 0; mf < 4; mf++)
#pragma unroll
        for (int nf = 0; nf < 4; nf++)
#pragma unroll
            for (int e = 0; e < 4; e++) c[mf][nf][e] = 0.0f;

#pragma unroll
    for (int ks = 0; ks < 4; ks++) {         // K=128 fp8, 32 per MMA
        uint32_t koff = (uint32_t)ks * 32;   // 32 fp8 = 32 B
        uint32_t a0[4], a1[4], a2[4], a3[4];
#pragma unroll
        for (int mf = 0; mf < 4; mf++)
            ldm_x4(a0[mf], a1[mf], a2[mf], a3[mf],
                   a_base + (uint32_t)mf * 16 * STRIDE + koff);
        uint32_t bl0[2], bl1[2], bl2[2], bl3[2];
#pragma unroll
        for (int nh = 0; nh < 2; nh++)
            ldm_x4(bl0[nh], bl1[nh], bl2[nh], bl3[nh],
                   b_base + (uint32_t)nh * 16 * STRIDE + koff);
#pragma unroll
        for (int mf = 0; mf < 4; mf++) {
#pragma unroll
            for (int nh = 0; nh < 2; nh++) {
                mma_fp8(c[mf][nh * 2][0], c[mf][nh * 2][1],
                        c[mf][nh * 2][2], c[mf][nh * 2][3],
                        a0[mf], a1[mf], a2[mf], a3[mf], bl0[nh], bl2[nh]);
                mma_fp8(c[mf][nh * 2 + 1][0], c[mf][nh * 2 + 1][1],
                        c[mf][nh * 2 + 1][2], c[mf][nh * 2 + 1][3],
                        a0[mf], a1[mf], a2[mf], a3[mf], bl1[nh], bl3[nh]);
            }
        }
    }

    // --- epilogue: exp + in-register row/col partial sums ---
    // elem map: c0:(r,cc) c1:(r,cc+1) c2:(r+8,cc) c3:(r+8,cc+1); r=l/4, cc=2(l%4)
    float rlo[4], rhi[4], ceven[4], codd[4];
#pragma unroll
    for (int i = 0; i < 4; i++) { ceven[i] = 0.0f; codd[i] = 0.0f; }
#pragma unroll
    for (int mf = 0; mf < 4; mf++) { rlo[mf] = 0.0f; rhi[mf] = 0.0f; }
#pragma unroll
    for (int mf = 0; mf < 4; mf++) {
#pragma unroll
        for (int nf = 0; nf < 4; nf++) {
            float e0 = __expf(c[mf][nf][0] * EXP_SCALE);
            float e1 = __expf(c[mf][nf][1] * EXP_SCALE);
            float e2 = __expf(c[mf][nf][2] * EXP_SCALE);
            float e3 = __expf(c[mf][nf][3] * EXP_SCALE);
            rlo[mf] += e0 + e1;
            rhi[mf] += e2 + e3;
            ceven[nf] += e0 + e2;
            codd[nf]  += e1 + e3;
        }
    }
#pragma unroll
    for (int mf = 0; mf < 4; mf++) {
#pragma unroll
        for (int o = 1; o <= 2; o <<= 1) {
            rlo[mf] += __shfl_xor_sync(0xffffffffu, rlo[mf], o);
            rhi[mf] += __shfl_xor_sync(0xffffffffu, rhi[mf], o);
        }
        if ((l & 3) == 0) {
            int r = m_base + mf * 16 + (l >> 2);
            atomicAdd(&srow[r], rlo[mf]);
            atomicAdd(&srow[r + 8], rhi[mf]);
        }
    }
#pragma unroll
    for (int nf = 0; nf < 4; nf++) {
#pragma unroll
        for (int o = 4; o <= 16; o <<= 1) {
            ceven[nf] += __shfl_xor_sync(0xffffffffu, ceven[nf], o);
            codd[nf]  += __shfl_xor_sync(0xffffffffu, codd[nf], o);
        }
        if (l < 4) {
            int cc = n_base + nf * 8 + 2 * l;
            atomicAdd(&scol[cc], ceven[nf]);
            atomicAdd(&scol[cc + 1], codd[nf]);
        }
    }
    __syncthreads();

    if (tid < TILE) {
        atomicAdd(&g_rowsum[rowBase + tid], srow[tid]);
        atomicAdd(&g_colsum[colBase + tid], scol[tid]);
    }
}

// ---------------------------------------------------------------------------
// Kernel 3: loss = ( sum log(rowsum)+log(colsum) - (2/T) sum pos ) / 2B
// ---------------------------------------------------------------------------
__global__ void final_kernel(float* __restrict__ out) {
    int t = threadIdx.x;
    double acc = 0.0;
    for (int i = t; i < NB; i += 256) {
        acc += (double)__logf(g_rowsum[i]) + (double)__logf(g_colsum[i])
             - 8.0 * (double)g_pos[i];                        // 2/T = 8
    }
    __shared__ double sd[256];
    sd[t] = acc;
    __syncthreads();
#pragma unroll
    for (int o = 128; o > 0; o >>= 1) {
        if (t < o) sd[t] += sd[t + o];
        __syncthreads();
    }
    if (t == 0) out[0] = (float)(sd[0] / (2.0 * NB));
}

extern "C" void kernel_launch(void* const* d_in, const int* in_sizes, int n_in,
                              void* d_out, int out_size) {
    const float* emb_i = (const float*)d_in[0];
    const float* emb_j = (const float*)d_in[1];
    float* out = (float*)d_out;

    cudaFuncSetAttribute(sim_kernel, cudaFuncAttributeMaxDynamicSharedMemorySize, SM_TOTAL);

    norm_kernel<<<NB / 8, 256>>>(emb_i, emb_j);
    dim3 grid(NB / TILE, NB / TILE);       // 32 x 32
    sim_kernel<<<grid, 256, SM_TOTAL>>>();
    final_kernel<<<1, 256>>>(out);
}

// round 6
// speedup vs baseline: 1.5908x; 1.2688x over previous
#include <cuda_runtime.h>
#include <cuda_bf16.h>
#include <math.h>
#include <cstdint>

#define NB 4096
#define ND 128
#define TILE 128
#define NT 1024                 // 32 x 32 tiles
#define GRID_SIM 296            // 2 CTAs per SM, persistent
#define STRIDE 144              // smem bytes per 128-col fp8 row (128 + 16 pad)
#define SM_TILE (128 * STRIDE)  // 18432 B per tile
#define BUF_BYTES (2 * SM_TILE) // A + B = 36864 B
#define SM_TOTAL (2 * BUF_BYTES)// double buffered = 73728 B
#define EXP_SCALE 0.015625f     // (1/T) / 256 = 4/256 (z scaled by 16 each side)

// ---------------- scratch (no allocations allowed) ----------------
__device__ __align__(16) uint32_t g_zi_f8[NB * 32];  // e4m3 z_i*16, 4 per uint
__device__ __align__(16) uint32_t g_zj_f8[NB * 32];  // e4m3 z_j*16
__device__ float g_rowsum[NB];
__device__ float g_colsum[NB];
__device__ float g_pos[NB];

__device__ __forceinline__ uint32_t smem_u32(const void* p) {
    uint32_t a;
    asm("{ .reg .u64 t; cvta.to.shared.u64 t, %1; cvt.u32.u64 %0, t; }" : "=r"(a) : "l"(p));
    return a;
}
__device__ __forceinline__ void cp16(uint32_t dst, const void* src) {
    asm volatile("cp.async.cg.shared.global [%0], [%1], 16;" :: "r"(dst), "l"(src));
}
__device__ __forceinline__ void ldm_x4(uint32_t& r0, uint32_t& r1, uint32_t& r2,
                                       uint32_t& r3, uint32_t addr) {
    asm volatile("ldmatrix.sync.aligned.m8n8.x4.shared.b16 {%0,%1,%2,%3}, [%4];"
                 : "=r"(r0), "=r"(r1), "=r"(r2), "=r"(r3) : "r"(addr));
}
__device__ __forceinline__ void mma_fp8(float& c0, float& c1, float& c2, float& c3,
                                        uint32_t a0, uint32_t a1, uint32_t a2, uint32_t a3,
                                        uint32_t b0, uint32_t b1) {
    asm volatile("mma.sync.aligned.m16n8k32.row.col.f32.e4m3.e4m3.f32 "
                 "{%0,%1,%2,%3}, {%4,%5,%6,%7}, {%8,%9}, {%0,%1,%2,%3};"
                 : "+f"(c0), "+f"(c1), "+f"(c2), "+f"(c3)
                 : "r"(a0), "r"(a1), "r"(a2), "r"(a3), "r"(b0), "r"(b1));
}
__device__ __forceinline__ uint32_t pack_e4m3(float x, float y, float z, float w) {
    uint16_t lo, hi;
    asm("cvt.rn.satfinite.e4m3x2.f32 %0, %1, %2;" : "=h"(lo) : "f"(y), "f"(x));
    asm("cvt.rn.satfinite.e4m3x2.f32 %0, %1, %2;" : "=h"(hi) : "f"(w), "f"(z));
    return (uint32_t)lo | ((uint32_t)hi << 16);
}

// ---------------------------------------------------------------------------
// Kernel 1: warp-per-row L2 normalize, write e4m3 z*16, fp32 positives, zero sums
// ---------------------------------------------------------------------------
__global__ void __launch_bounds__(256) norm_kernel(const float* __restrict__ emb_i,
                                                   const float* __restrict__ emb_j) {
    int lane = threadIdx.x & 31;
    int row = blockIdx.x * 8 + (threadIdx.x >> 5);
    const float4 a = ((const float4*)emb_i)[row * 32 + lane];
    const float4 b = ((const float4*)emb_j)[row * 32 + lane];
    float ssi = a.x * a.x + a.y * a.y + a.z * a.z + a.w * a.w;
    float ssj = b.x * b.x + b.y * b.y + b.z * b.z + b.w * b.w;
    float dot = a.x * b.x + a.y * b.y + a.z * b.z + a.w * b.w;
#pragma unroll
    for (int o = 16; o > 0; o >>= 1) {
        ssi += __shfl_xor_sync(0xffffffffu, ssi, o);
        ssj += __shfl_xor_sync(0xffffffffu, ssj, o);
        dot += __shfl_xor_sync(0xffffffffu, dot, o);
    }
    float inv_i = 1.0f / fmaxf(sqrtf(ssi), 1e-12f);
    float inv_j = 1.0f / fmaxf(sqrtf(ssj), 1e-12f);
    float si = inv_i * 16.0f;   // scale into e4m3 normal range
    float sj = inv_j * 16.0f;

    g_zi_f8[row * 32 + lane] = pack_e4m3(a.x * si, a.y * si, a.z * si, a.w * si);
    g_zj_f8[row * 32 + lane] = pack_e4m3(b.x * sj, b.y * sj, b.z * sj, b.w * sj);
    if (lane == 0) {
        g_pos[row]    = dot * inv_i * inv_j;   // exact fp32 positive
        g_rowsum[row] = 0.0f;
        g_colsum[row] = 0.0f;
    }
}

// ---------------------------------------------------------------------------
// Kernel 2: persistent, cp.async double-buffered fp8 MMA + fused exp/row/col.
// 296 CTAs x 256 threads; each CTA streams 3-4 tiles of 128x128.
// ---------------------------------------------------------------------------
__device__ __forceinline__ void prefetch_tile(int t, uint32_t dst, int tid) {
    int bx = t & 31, by = t >> 5;
    const char* srcA = (const char*)g_zi_f8 + (size_t)by * 128 * 128;
    const char* srcB = (const char*)g_zj_f8 + (size_t)bx * 128 * 128;
#pragma unroll
    for (int it = 0; it < 4; it++) {
        int i = it * 256 + tid;                 // [0,1024): row=i>>3, chunk=i&7
        uint32_t soff = (uint32_t)(i >> 3) * STRIDE + (uint32_t)(i & 7) * 16;
        cp16(dst + soff, srcA + (size_t)i * 16);
        cp16(dst + SM_TILE + soff, srcB + (size_t)i * 16);
    }
    asm volatile("cp.async.commit_group;" ::: "memory");
}

__global__ void __launch_bounds__(256, 2) sim_kernel() {
    extern __shared__ char smem[];
    __shared__ float srow[TILE];
    __shared__ float scol[TILE];

    uint32_t sbase = smem_u32(smem);
    int tid = threadIdx.x;
    int wid = tid >> 5;
    int l = tid & 31;
    int m_base = (wid & 1) * 64;
    int n_base = (wid >> 1) * 32;
    uint32_t lrow  = (uint32_t)(((l >> 3) & 1) * 8 + (l & 7));
    uint32_t lcolb = (uint32_t)((l >> 4) * 16);

    if (tid < TILE) { srow[tid] = 0.0f; scol[tid] = 0.0f; }

    int t = blockIdx.x;
    prefetch_tile(t, sbase, tid);                 // buffer 0
    int buf = 0;

    for (; t < NT; t += GRID_SIM) {
        uint32_t cur = sbase + (uint32_t)buf * BUF_BYTES;
        int tn = t + GRID_SIM;
        if (tn < NT) {
            prefetch_tile(tn, sbase + (uint32_t)(buf ^ 1) * BUF_BYTES, tid);
            asm volatile("cp.async.wait_group 1;" ::: "memory");
        } else {
            asm volatile("cp.async.wait_group 0;" ::: "memory");
        }
        __syncthreads();                          // cur tile resident; srow/scol reset

        uint32_t a_base = cur + (m_base + lrow) * STRIDE + lcolb;
        uint32_t b_base = cur + SM_TILE + (n_base + lrow) * STRIDE + lcolb;

        float c[4][4][4];
#pragma unroll
        for (int mf = 0; mf < 4; mf++)
#pragma unroll
            for (int nf = 0; nf < 4; nf++)
#pragma unroll
                for (int e = 0; e < 4; e++) c[mf][nf][e] = 0.0f;

#pragma unroll
        for (int ks = 0; ks < 4; ks++) {          // K=128 fp8, 32 per MMA
            uint32_t koff = (uint32_t)ks * 32;
            uint32_t a0[4], a1[4], a2[4], a3[4];
#pragma unroll
            for (int mf = 0; mf < 4; mf++)
                ldm_x4(a0[mf], a1[mf], a2[mf], a3[mf],
                       a_base + (uint32_t)mf * 16 * STRIDE + koff);
            uint32_t bl0[2], bl1[2], bl2[2], bl3[2];
#pragma unroll
            for (int nh = 0; nh < 2; nh++)
                ldm_x4(bl0[nh], bl1[nh], bl2[nh], bl3[nh],
                       b_base + (uint32_t)nh * 16 * STRIDE + koff);
#pragma unroll
            for (int mf = 0; mf < 4; mf++) {
#pragma unroll
                for (int nh = 0; nh < 2; nh++) {
                    mma_fp8(c[mf][nh * 2][0], c[mf][nh * 2][1],
                            c[mf][nh * 2][2], c[mf][nh * 2][3],
                            a0[mf], a1[mf], a2[mf], a3[mf], bl0[nh], bl2[nh]);
                    mma_fp8(c[mf][nh * 2 + 1][0], c[mf][nh * 2 + 1][1],
                            c[mf][nh * 2 + 1][2], c[mf][nh * 2 + 1][3],
                            a0[mf], a1[mf], a2[mf], a3[mf], bl1[nh], bl3[nh]);
                }
            }
        }

        // --- epilogue: exp + in-register row/col partial sums ---
        // elem map: c0:(r,cc) c1:(r,cc+1) c2:(r+8,cc) c3:(r+8,cc+1); r=l/4, cc=2(l%4)
        float rlo[4], rhi[4], ceven[4], codd[4];
#pragma unroll
        for (int i = 0; i < 4; i++) { ceven[i] = 0.0f; codd[i] = 0.0f; }
#pragma unroll
        for (int mf = 0; mf < 4; mf++) { rlo[mf] = 0.0f; rhi[mf] = 0.0f; }
#pragma unroll
        for (int mf = 0; mf < 4; mf++) {
#pragma unroll
            for (int nf = 0; nf < 4; nf++) {
                float e0 = __expf(c[mf][nf][0] * EXP_SCALE);
                float e1 = __expf(c[mf][nf][1] * EXP_SCALE);
                float e2 = __expf(c[mf][nf][2] * EXP_SCALE);
                float e3 = __expf(c[mf][nf][3] * EXP_SCALE);
                rlo[mf] += e0 + e1;
                rhi[mf] += e2 + e3;
                ceven[nf] += e0 + e2;
                codd[nf]  += e1 + e3;
            }
        }
#pragma unroll
        for (int mf = 0; mf < 4; mf++) {
#pragma unroll
            for (int o = 1; o <= 2; o <<= 1) {
                rlo[mf] += __shfl_xor_sync(0xffffffffu, rlo[mf], o);
                rhi[mf] += __shfl_xor_sync(0xffffffffu, rhi[mf], o);
            }
            if ((l & 3) == 0) {
                int r = m_base + mf * 16 + (l >> 2);
                atomicAdd(&srow[r], rlo[mf]);
                atomicAdd(&srow[r + 8], rhi[mf]);
            }
        }
#pragma unroll
        for (int nf = 0; nf < 4; nf++) {
#pragma unroll
            for (int o = 4; o <= 16; o <<= 1) {
                ceven[nf] += __shfl_xor_sync(0xffffffffu, ceven[nf], o);
                codd[nf]  += __shfl_xor_sync(0xffffffffu, codd[nf], o);
            }
            if (l < 4) {
                int cc = n_base + nf * 8 + 2 * l;
                atomicAdd(&scol[cc], ceven[nf]);
                atomicAdd(&scol[cc + 1], codd[nf]);
            }
        }
        __syncthreads();

        if (tid < TILE) {
            atomicAdd(&g_rowsum[(t >> 5) * TILE + tid], srow[tid]);
            atomicAdd(&g_colsum[(t & 31) * TILE + tid], scol[tid]);
            srow[tid] = 0.0f;                     // reset for next tile
            scol[tid] = 0.0f;
        }
        buf ^= 1;
        // next iteration's leading __syncthreads orders the reset vs. new atomics
    }
}

// ---------------------------------------------------------------------------
// Kernel 3: loss = ( sum log(rowsum)+log(colsum) - (2/T) sum pos ) / 2B
// ---------------------------------------------------------------------------
__global__ void final_kernel(float* __restrict__ out) {
    int t = threadIdx.x;
    double acc = 0.0;
    for (int i = t; i < NB; i += 256) {
        acc += (double)__logf(g_rowsum[i]) + (double)__logf(g_colsum[i])
             - 8.0 * (double)g_pos[i];                        // 2/T = 8
    }
    __shared__ double sd[256];
    sd[t] = acc;
    __syncthreads();
#pragma unroll
    for (int o = 128; o > 0; o >>= 1) {
        if (t < o) sd[t] += sd[t + o];
        __syncthreads();
    }
    if (t == 0) out[0] = (float)(sd[0] / (2.0 * NB));
}

extern "C" void kernel_launch(void* const* d_in, const int* in_sizes, int n_in,
                              void* d_out, int out_size) {
    const float* emb_i = (const float*)d_in[0];
    const float* emb_j = (const float*)d_in[1];
    float* out = (float*)d_out;

    cudaFuncSetAttribute(sim_kernel, cudaFuncAttributeMaxDynamicSharedMemorySize, SM_TOTAL);

    norm_kernel<<<NB / 8, 256>>>(emb_i, emb_j);
    sim_kernel<<<GRID_SIM, 256, SM_TOTAL>>>();
    final_kernel<<<1, 256>>>(out);
}

// round 7
// speedup vs baseline: 1.6003x; 1.0060x over previous
#include <cuda_runtime.h>
#include <cuda_bf16.h>
#include <cuda_fp16.h>
#include <math.h>
#include <cstdint>

#define NB 4096
#define ND 128
#define TILE 128
#define NT 1024                 // 32 x 32 tiles
#define GRID_SIM 296            // 2 CTAs per SM, persistent
#define STRIDE 144              // smem bytes per 128-col fp8 row (128 + 16 pad)
#define SM_TILE (128 * STRIDE)  // 18432 B per tile
#define BUF_BYTES (2 * SM_TILE) // A + B = 36864 B
#define SM_TOTAL (2 * BUF_BYTES)// double buffered = 73728 B
#define EXP_SCALE 0.015625f     // (1/T) / 256 = 4/256 (z scaled by 16 each side)

// ---------------- scratch (no allocations allowed) ----------------
__device__ __align__(16) uint32_t g_zi_f8[NB * 32];  // e4m3 z_i*16, 4 per uint
__device__ __align__(16) uint32_t g_zj_f8[NB * 32];  // e4m3 z_j*16
__device__ float g_rowsum[NB];
__device__ float g_colsum[NB];
__device__ float g_pos[NB];

__device__ __forceinline__ uint32_t smem_u32(const void* p) {
    uint32_t a;
    asm("{ .reg .u64 t; cvta.to.shared.u64 t, %1; cvt.u32.u64 %0, t; }" : "=r"(a) : "l"(p));
    return a;
}
__device__ __forceinline__ void cp16(uint32_t dst, const void* src) {
    asm volatile("cp.async.cg.shared.global [%0], [%1], 16;" :: "r"(dst), "l"(src));
}
__device__ __forceinline__ void ldm_x4(uint32_t& r0, uint32_t& r1, uint32_t& r2,
                                       uint32_t& r3, uint32_t addr) {
    asm volatile("ldmatrix.sync.aligned.m8n8.x4.shared.b16 {%0,%1,%2,%3}, [%4];"
                 : "=r"(r0), "=r"(r1), "=r"(r2), "=r"(r3) : "r"(addr));
}
// fp8 MMA with f16 accumulators (fast-accum path): D,C packed half2
__device__ __forceinline__ void mma_fp8_h(uint32_t& c0, uint32_t& c1,
                                          uint32_t a0, uint32_t a1, uint32_t a2, uint32_t a3,
                                          uint32_t b0, uint32_t b1) {
    asm volatile("mma.sync.aligned.m16n8k32.row.col.f16.e4m3.e4m3.f16 "
                 "{%0,%1}, {%2,%3,%4,%5}, {%6,%7}, {%0,%1};"
                 : "+r"(c0), "+r"(c1)
                 : "r"(a0), "r"(a1), "r"(a2), "r"(a3), "r"(b0), "r"(b1));
}
__device__ __forceinline__ uint32_t pack_e4m3(float x, float y, float z, float w) {
    uint16_t lo, hi;
    asm("cvt.rn.satfinite.e4m3x2.f32 %0, %1, %2;" : "=h"(lo) : "f"(y), "f"(x));
    asm("cvt.rn.satfinite.e4m3x2.f32 %0, %1, %2;" : "=h"(hi) : "f"(w), "f"(z));
    return (uint32_t)lo | ((uint32_t)hi << 16);
}

// ---------------------------------------------------------------------------
// Kernel 1: warp-per-row L2 normalize, write e4m3 z*16, fp32 positives, zero sums
// ---------------------------------------------------------------------------
__global__ void __launch_bounds__(256) norm_kernel(const float* __restrict__ emb_i,
                                                   const float* __restrict__ emb_j) {
    int lane = threadIdx.x & 31;
    int row = blockIdx.x * 8 + (threadIdx.x >> 5);
    const float4 a = ((const float4*)emb_i)[row * 32 + lane];
    const float4 b = ((const float4*)emb_j)[row * 32 + lane];
    float ssi = a.x * a.x + a.y * a.y + a.z * a.z + a.w * a.w;
    float ssj = b.x * b.x + b.y * b.y + b.z * b.z + b.w * b.w;
    float dot = a.x * b.x + a.y * b.y + a.z * b.z + a.w * b.w;
#pragma unroll
    for (int o = 16; o > 0; o >>= 1) {
        ssi += __shfl_xor_sync(0xffffffffu, ssi, o);
        ssj += __shfl_xor_sync(0xffffffffu, ssj, o);
        dot += __shfl_xor_sync(0xffffffffu, dot, o);
    }
    float inv_i = 1.0f / fmaxf(sqrtf(ssi), 1e-12f);
    float inv_j = 1.0f / fmaxf(sqrtf(ssj), 1e-12f);
    float si = inv_i * 16.0f;   // scale into e4m3 normal range
    float sj = inv_j * 16.0f;

    g_zi_f8[row * 32 + lane] = pack_e4m3(a.x * si, a.y * si, a.z * si, a.w * si);
    g_zj_f8[row * 32 + lane] = pack_e4m3(b.x * sj, b.y * sj, b.z * sj, b.w * sj);
    if (lane == 0) {
        g_pos[row]    = dot * inv_i * inv_j;   // exact fp32 positive
        g_rowsum[row] = 0.0f;
        g_colsum[row] = 0.0f;
    }
}

// ---------------------------------------------------------------------------
// Kernel 2: persistent, cp.async double-buffered fp8 MMA (f16 accum) + epilogue
// ---------------------------------------------------------------------------
__device__ __forceinline__ void prefetch_tile(int t, uint32_t dst, int tid) {
    int bx = t & 31, by = t >> 5;
    const char* srcA = (const char*)g_zi_f8 + (size_t)by * 128 * 128;
    const char* srcB = (const char*)g_zj_f8 + (size_t)bx * 128 * 128;
#pragma unroll
    for (int it = 0; it < 4; it++) {
        int i = it * 256 + tid;                 // [0,1024): row=i>>3, chunk=i&7
        uint32_t soff = (uint32_t)(i >> 3) * STRIDE + (uint32_t)(i & 7) * 16;
        cp16(dst + soff, srcA + (size_t)i * 16);
        cp16(dst + SM_TILE + soff, srcB + (size_t)i * 16);
    }
    asm volatile("cp.async.commit_group;" ::: "memory");
}

__global__ void __launch_bounds__(256, 2) sim_kernel() {
    extern __shared__ char smem[];
    __shared__ float srow[TILE];
    __shared__ float scol[TILE];

    uint32_t sbase = smem_u32(smem);
    int tid = threadIdx.x;
    int wid = tid >> 5;
    int l = tid & 31;
    int m_base = (wid & 1) * 64;
    int n_base = (wid >> 1) * 32;
    uint32_t lrow  = (uint32_t)(((l >> 3) & 1) * 8 + (l & 7));
    uint32_t lcolb = (uint32_t)((l >> 4) * 16);

    if (tid < TILE) { srow[tid] = 0.0f; scol[tid] = 0.0f; }

    int t = blockIdx.x;
    prefetch_tile(t, sbase, tid);                 // buffer 0
    int buf = 0;

    for (; t < NT; t += GRID_SIM) {
        uint32_t cur = sbase + (uint32_t)buf * BUF_BYTES;
        int tn = t + GRID_SIM;
        if (tn < NT) {
            prefetch_tile(tn, sbase + (uint32_t)(buf ^ 1) * BUF_BYTES, tid);
            asm volatile("cp.async.wait_group 1;" ::: "memory");
        } else {
            asm volatile("cp.async.wait_group 0;" ::: "memory");
        }
        __syncthreads();                          // cur tile resident; srow/scol reset

        uint32_t a_base = cur + (m_base + lrow) * STRIDE + lcolb;
        uint32_t b_base = cur + SM_TILE + (n_base + lrow) * STRIDE + lcolb;

        uint32_t c[4][4][2];                      // packed half2 accumulators
#pragma unroll
        for (int mf = 0; mf < 4; mf++)
#pragma unroll
            for (int nf = 0; nf < 4; nf++) { c[mf][nf][0] = 0u; c[mf][nf][1] = 0u; }

#pragma unroll
        for (int ks = 0; ks < 4; ks++) {          // K=128 fp8, 32 per MMA
            uint32_t koff = (uint32_t)ks * 32;
            uint32_t a0[4], a1[4], a2[4], a3[4];
#pragma unroll
            for (int mf = 0; mf < 4; mf++)
                ldm_x4(a0[mf], a1[mf], a2[mf], a3[mf],
                       a_base + (uint32_t)mf * 16 * STRIDE + koff);
            uint32_t bl0[2], bl1[2], bl2[2], bl3[2];
#pragma unroll
            for (int nh = 0; nh < 2; nh++)
                ldm_x4(bl0[nh], bl1[nh], bl2[nh], bl3[nh],
                       b_base + (uint32_t)nh * 16 * STRIDE + koff);
#pragma unroll
            for (int mf = 0; mf < 4; mf++) {
#pragma unroll
                for (int nh = 0; nh < 2; nh++) {
                    mma_fp8_h(c[mf][nh * 2][0], c[mf][nh * 2][1],
                              a0[mf], a1[mf], a2[mf], a3[mf], bl0[nh], bl2[nh]);
                    mma_fp8_h(c[mf][nh * 2 + 1][0], c[mf][nh * 2 + 1][1],
                              a0[mf], a1[mf], a2[mf], a3[mf], bl1[nh], bl3[nh]);
                }
            }
        }

        // --- epilogue: unpack half2, exp, in-register row/col partial sums ---
        // c0 -> (r,cc),(r,cc+1); c1 -> (r+8,cc),(r+8,cc+1); r=l/4, cc=2(l%4)
        float rlo[4], rhi[4], ceven[4], codd[4];
#pragma unroll
        for (int i = 0; i < 4; i++) { ceven[i] = 0.0f; codd[i] = 0.0f; }
#pragma unroll
        for (int mf = 0; mf < 4; mf++) { rlo[mf] = 0.0f; rhi[mf] = 0.0f; }
#pragma unroll
        for (int mf = 0; mf < 4; mf++) {
#pragma unroll
            for (int nf = 0; nf < 4; nf++) {
                float2 lo = __half22float2(*(__half2*)&c[mf][nf][0]);
                float2 hi = __half22float2(*(__half2*)&c[mf][nf][1]);
                float e0 = __expf(lo.x * EXP_SCALE);
                float e1 = __expf(lo.y * EXP_SCALE);
                float e2 = __expf(hi.x * EXP_SCALE);
                float e3 = __expf(hi.y * EXP_SCALE);
                rlo[mf] += e0 + e1;
                rhi[mf] += e2 + e3;
                ceven[nf] += e0 + e2;
                codd[nf]  += e1 + e3;
            }
        }
#pragma unroll
        for (int mf = 0; mf < 4; mf++) {
#pragma unroll
            for (int o = 1; o <= 2; o <<= 1) {
                rlo[mf] += __shfl_xor_sync(0xffffffffu, rlo[mf], o);
                rhi[mf] += __shfl_xor_sync(0xffffffffu, rhi[mf], o);
            }
            if ((l & 3) == 0) {
                int r = m_base + mf * 16 + (l >> 2);
                atomicAdd(&srow[r], rlo[mf]);
                atomicAdd(&srow[r + 8], rhi[mf]);
            }
        }
#pragma unroll
        for (int nf = 0; nf < 4; nf++) {
#pragma unroll
            for (int o = 4; o <= 16; o <<= 1) {
                ceven[nf] += __shfl_xor_sync(0xffffffffu, ceven[nf], o);
                codd[nf]  += __shfl_xor_sync(0xffffffffu, codd[nf], o);
            }
            if (l < 4) {
                int cc = n_base + nf * 8 + 2 * l;
                atomicAdd(&scol[cc], ceven[nf]);
                atomicAdd(&scol[cc + 1], codd[nf]);
            }
        }
        __syncthreads();

        if (tid < TILE) {
            atomicAdd(&g_rowsum[(t >> 5) * TILE + tid], srow[tid]);
            atomicAdd(&g_colsum[(t & 31) * TILE + tid], scol[tid]);
            srow[tid] = 0.0f;                     // reset for next tile
            scol[tid] = 0.0f;
        }
        buf ^= 1;
        // next iteration's leading __syncthreads orders the reset vs. new atomics
    }
}

// ---------------------------------------------------------------------------
// Kernel 3: loss = ( sum log(rowsum)+log(colsum) - (2/T) sum pos ) / 2B
// ---------------------------------------------------------------------------
__global__ void final_kernel(float* __restrict__ out) {
    int t = threadIdx.x;
    double acc = 0.0;
    for (int i = t; i < NB; i += 256) {
        acc += (double)__logf(g_rowsum[i]) + (double)__logf(g_colsum[i])
             - 8.0 * (double)g_pos[i];                        // 2/T = 8
    }
    __shared__ double sd[256];
    sd[t] = acc;
    __syncthreads();
#pragma unroll
    for (int o = 128; o > 0; o >>= 1) {
        if (t < o) sd[t] += sd[t + o];
        __syncthreads();
    }
    if (t == 0) out[0] = (float)(sd[0] / (2.0 * NB));
}

extern "C" void kernel_launch(void* const* d_in, const int* in_sizes, int n_in,
                              void* d_out, int out_size) {
    const float* emb_i = (const float*)d_in[0];
    const float* emb_j = (const float*)d_in[1];
    float* out = (float*)d_out;

    cudaFuncSetAttribute(sim_kernel, cudaFuncAttributeMaxDynamicSharedMemorySize, SM_TOTAL);

    norm_kernel<<<NB / 8, 256>>>(emb_i, emb_j);
    sim_kernel<<<GRID_SIM, 256, SM_TOTAL>>>();
    final_kernel<<<1, 256>>>(out);
}